// round 3
// baseline (speedup 1.0000x reference)
#include <cuda_runtime.h>
#include <math.h>

// ---------------------------------------------------------------------------
// Problem constants
// ---------------------------------------------------------------------------
#define MTOK   8192          // 8 * 1024 tokens
#define DIMC   768
#define HEADS  12
#define HD     64
#define KPARTS 64
#define MLPH   3072
#define NTOK   1024
#define BATCH  8
#define X_ELEMS (MTOK * DIMC)      // 6291456
#define DMAP_ELEMS (MTOK * KPARTS) // 524288

// Attention processed in Z-chunks to bound the scores scratch.
#define ZCHUNK 48            // (b,h) pairs per chunk; 96 total -> 2 chunks

// ---------------------------------------------------------------------------
// Scratch (device globals; no allocation allowed)
// ---------------------------------------------------------------------------
__device__ float g_n1   [MTOK * DIMC];
__device__ float g_rinv [MTOK];
__device__ float g_pinv [KPARTS];
__device__ float g_qkv  [MTOK * 3 * DIMC];
__device__ float g_scores[(long long)ZCHUNK * NTOK * NTOK]; // 48M floats = 192MB
__device__ float g_att  [MTOK * DIMC];
__device__ float g_y    [MTOK * DIMC];
__device__ float g_h1   [MTOK * KPARTS];
__device__ float g_zin  [MTOK * DIMC];
__device__ float g_xr   [MTOK * DIMC];
__device__ float g_h    [MTOK * MLPH];

// ---------------------------------------------------------------------------
// Reductions
// ---------------------------------------------------------------------------
__device__ __forceinline__ float blk_sum(float v, float* sbuf) {
    #pragma unroll
    for (int o = 16; o; o >>= 1) v += __shfl_xor_sync(0xffffffffu, v, o);
    if ((threadIdx.x & 31) == 0) sbuf[threadIdx.x >> 5] = v;
    __syncthreads();
    if (threadIdx.x == 0) {
        float r = sbuf[0];
        int nw = blockDim.x >> 5;
        for (int i = 1; i < nw; i++) r += sbuf[i];
        sbuf[0] = r;
    }
    __syncthreads();
    float r = sbuf[0];
    __syncthreads();
    return r;
}

__device__ __forceinline__ float blk_max(float v, float* sbuf) {
    #pragma unroll
    for (int o = 16; o; o >>= 1) v = fmaxf(v, __shfl_xor_sync(0xffffffffu, v, o));
    if ((threadIdx.x & 31) == 0) sbuf[threadIdx.x >> 5] = v;
    __syncthreads();
    if (threadIdx.x == 0) {
        float r = sbuf[0];
        int nw = blockDim.x >> 5;
        for (int i = 1; i < nw; i++) r = fmaxf(r, sbuf[i]);
        sbuf[0] = r;
    }
    __syncthreads();
    float r = sbuf[0];
    __syncthreads();
    return r;
}

// ---------------------------------------------------------------------------
// LayerNorm (row = 768). Optionally also emits 1/||y|| per row (for cosine map).
// ---------------------------------------------------------------------------
__global__ void ln_kernel(const float* __restrict__ x, const float* __restrict__ g,
                          const float* __restrict__ b, float* __restrict__ out,
                          float* __restrict__ rinv) {
    __shared__ float sbuf[8];
    long long row = blockIdx.x;
    const float* xr = x + row * DIMC;
    float v[3];
    float s = 0.f;
    #pragma unroll
    for (int k = 0; k < 3; k++) { v[k] = xr[threadIdx.x + 256 * k]; s += v[k]; }
    float mu = blk_sum(s, sbuf) * (1.f / DIMC);
    float s2 = 0.f;
    #pragma unroll
    for (int k = 0; k < 3; k++) { float d = v[k] - mu; s2 += d * d; }
    float var = blk_sum(s2, sbuf) * (1.f / DIMC);
    float rs = rsqrtf(var + 1e-5f);
    float sq = 0.f;
    #pragma unroll
    for (int k = 0; k < 3; k++) {
        int c = threadIdx.x + 256 * k;
        float yv = (v[k] - mu) * rs * g[c] + b[c];
        out[row * DIMC + c] = yv;
        sq += yv * yv;
    }
    if (rinv) {
        float nn = blk_sum(sq, sbuf);
        if (threadIdx.x == 0) rinv[row] = 1.f / sqrtf(nn);
    }
}

// 1/||P_k|| for each of the 64 part vectors (len 768)
__global__ void rownorm_kernel(const float* __restrict__ P, float* __restrict__ pinv) {
    __shared__ float sbuf[8];
    const float* r = P + (long long)blockIdx.x * DIMC;
    float s = 0.f;
    for (int k = threadIdx.x; k < DIMC; k += 256) { float v = r[k]; s += v * v; }
    s = blk_sum(s, sbuf);
    if (threadIdx.x == 0) pinv[blockIdx.x] = 1.f / sqrtf(s);
}

// Row softmax over 1024 columns, in place.
__global__ void softmax1024(float* __restrict__ S) {
    __shared__ float sbuf[8];
    float4* row = (float4*)(S + (long long)blockIdx.x * NTOK);
    float4 v = row[threadIdx.x];
    float mx = fmaxf(fmaxf(v.x, v.y), fmaxf(v.z, v.w));
    mx = blk_max(mx, sbuf);
    v.x = expf(v.x - mx); v.y = expf(v.y - mx);
    v.z = expf(v.z - mx); v.w = expf(v.w - mx);
    float s = blk_sum(v.x + v.y + v.z + v.w, sbuf);
    float inv = 1.f / s;
    v.x *= inv; v.y *= inv; v.z *= inv; v.w *= inv;
    row[threadIdx.x] = v;
}

// ---------------------------------------------------------------------------
// Generic tiled SGEMM.
//   TRB=true : C = alpha * A[M,K] * B[N,K]^T   (weights, Q·K^T)
//   TRB=false: C = alpha * A[M,K] * B[K,N]     (P·V)
//
// Batching over blockIdx.z. Global z index = blockIdx.z + zoff, decomposed as
// (zb = z/NH, zh = z%NH). Per-operand addressing:
//   aLocal: A += blockIdx.z * sAh            (chunk-local scratch)
//   else  : A += zb * sAb + zh * sAh         (global layout)
//   cLocal: C += blockIdx.z * sCh
//   else  : C += zb * sCb + zh * sCh
//   B always global: B += zb * sBb + zh * sBh
//
// EPI: 0 none, 1 exact GELU, 2 row*col scale (cosine), 3 residual add(s).
// Bias applied whenever bias != nullptr.
// ---------------------------------------------------------------------------
template<int BM, int BN, int BK, int TM, int TN, bool TRB, int EPI>
__global__ void __launch_bounds__((BM / TM) * (BN / TN))
sgemm_k(const float* __restrict__ A, const float* __restrict__ B, float* __restrict__ C,
        int K, int lda, int ldb, int ldc, int NH, int zoff, int aLocal, int cLocal,
        long long sAb, long long sAh, long long sBb, long long sBh,
        long long sCb, long long sCh,
        float alpha,
        const float* __restrict__ bias,
        const float* __restrict__ res1, const float* __restrict__ res2,
        const float* __restrict__ rowscale, const float* __restrict__ colscale) {
    constexpr int NT_ = (BM / TM) * (BN / TN);
    __shared__ float As[BK][BM + 4];
    __shared__ float Bs[BK][BN + 4];
    const int tid = threadIdx.x;
    const int bx = blockIdx.x, by = blockIdx.y;
    const int bzg = blockIdx.z + zoff;          // global (b,h) index
    const int zb = bzg / NH, zh = bzg % NH;

    const float* Ab = A
        + (aLocal ? (long long)blockIdx.z * sAh
                  : (long long)zb * sAb + (long long)zh * sAh)
        + (long long)by * BM * lda;
    const float* Bb = B + (long long)zb * sBb + (long long)zh * sBh +
                      (TRB ? (long long)bx * BN * ldb : (long long)(bx * BN));
    float* Cb = C
        + (cLocal ? (long long)blockIdx.z * sCh
                  : (long long)zb * sCb + (long long)zh * sCh)
        + (long long)by * BM * ldc + (long long)(bx * BN);

    constexpr int TX = BN / TN;
    const int tx = tid % TX, ty = tid / TX;

    float acc[TM][TN] = {};

    for (int k0 = 0; k0 < K; k0 += BK) {
        #pragma unroll
        for (int idx = tid; idx < BM * (BK / 4); idx += NT_) {
            int row = idx / (BK / 4), cc = idx % (BK / 4);
            float4 v = *(const float4*)(Ab + (long long)row * lda + k0 + 4 * cc);
            As[4 * cc + 0][row] = v.x; As[4 * cc + 1][row] = v.y;
            As[4 * cc + 2][row] = v.z; As[4 * cc + 3][row] = v.w;
        }
        if (TRB) {
            #pragma unroll
            for (int idx = tid; idx < BN * (BK / 4); idx += NT_) {
                int row = idx / (BK / 4), cc = idx % (BK / 4);
                float4 v = *(const float4*)(Bb + (long long)row * ldb + k0 + 4 * cc);
                Bs[4 * cc + 0][row] = v.x; Bs[4 * cc + 1][row] = v.y;
                Bs[4 * cc + 2][row] = v.z; Bs[4 * cc + 3][row] = v.w;
            }
        } else {
            #pragma unroll
            for (int idx = tid; idx < BK * (BN / 4); idx += NT_) {
                int row = idx / (BN / 4), cc = idx % (BN / 4);
                float4 v = *(const float4*)(Bb + (long long)(k0 + row) * ldb + 4 * cc);
                *(float4*)&Bs[row][4 * cc] = v;
            }
        }
        __syncthreads();
        #pragma unroll
        for (int k = 0; k < BK; k++) {
            float ar[TM], br[TN];
            #pragma unroll
            for (int i = 0; i < TM; i += 4)
                *(float4*)&ar[i] = *(const float4*)&As[k][ty * TM + i];
            #pragma unroll
            for (int j = 0; j < TN; j += 4)
                *(float4*)&br[j] = *(const float4*)&Bs[k][tx * TN + j];
            #pragma unroll
            for (int i = 0; i < TM; i++)
                #pragma unroll
                for (int j = 0; j < TN; j++)
                    acc[i][j] = fmaf(ar[i], br[j], acc[i][j]);
        }
        __syncthreads();
    }

    #pragma unroll
    for (int i = 0; i < TM; i++) {
        long long m = (long long)by * BM + ty * TM + i;
        #pragma unroll
        for (int j = 0; j < TN; j++) {
            int n = bx * BN + tx * TN + j;
            float v = acc[i][j] * alpha;
            if (bias) v += bias[n];
            if constexpr (EPI == 1)
                v = 0.5f * v * (1.f + erff(v * 0.70710678118654752f));
            if constexpr (EPI == 2)
                v *= rowscale[m] * colscale[n];
            if constexpr (EPI == 3) {
                v += res1[m * ldc + n];
                if (res2) v += res2[m * ldc + n];
            }
            Cb[(long long)(ty * TM + i) * ldc + tx * TN + j] = v;
        }
    }
}

// ---------------------------------------------------------------------------
// Host-side launcher helper
// ---------------------------------------------------------------------------
template<int BM, int BN, bool TRB, int EPI>
static void gemm_launch(const float* A, const float* B, float* C,
                        int Mrows, int Ncols, int K,
                        int lda, int ldb, int ldc,
                        int nbz, int NH, int zoff, int aLocal, int cLocal,
                        long long sAb, long long sAh, long long sBb, long long sBh,
                        long long sCb, long long sCh,
                        float alpha, const float* bias,
                        const float* res1, const float* res2,
                        const float* rs, const float* cs) {
    dim3 grid(Ncols / BN, Mrows / BM, nbz);
    dim3 blk((BM / 8) * (BN / 8));
    sgemm_k<BM, BN, 16, 8, 8, TRB, EPI><<<grid, blk>>>(
        A, B, C, K, lda, ldb, ldc, NH, zoff, aLocal, cLocal,
        sAb, sAh, sBb, sBh, sCb, sCh,
        alpha, bias, res1, res2, rs, cs);
}

// ---------------------------------------------------------------------------
// kernel_launch
// ---------------------------------------------------------------------------
extern "C" void kernel_launch(void* const* d_in, const int* in_sizes, int n_in,
                              void* d_out, int out_size) {
    const float* x        = (const float*)d_in[0];
    const float* ln1_g    = (const float*)d_in[1];
    const float* ln1_b    = (const float*)d_in[2];
    const float* qkv_w    = (const float*)d_in[3];
    const float* qkv_b    = (const float*)d_in[4];
    const float* proj_w   = (const float*)d_in[5];
    const float* proj_b   = (const float*)d_in[6];
    const float* c_qkv_w  = (const float*)d_in[7];
    const float* c_qkv_b  = (const float*)d_in[8];
    const float* c_proj_w = (const float*)d_in[9];
    const float* c_proj_b = (const float*)d_in[10];
    const float* cp_fc1_w = (const float*)d_in[11];
    const float* cp_fc1_b = (const float*)d_in[12];
    const float* cp_fc2_w = (const float*)d_in[13];
    const float* cp_fc2_b = (const float*)d_in[14];
    const float* P        = (const float*)d_in[15];
    const float* ln2_g    = (const float*)d_in[16];
    const float* ln2_b    = (const float*)d_in[17];
    const float* fc1_w    = (const float*)d_in[18];
    const float* fc1_b    = (const float*)d_in[19];
    const float* fc2_w    = (const float*)d_in[20];
    const float* fc2_b    = (const float*)d_in[21];

    float *n1, *rinv, *pinv, *qkv, *scores, *att, *y, *h1, *zin, *xr, *h;
    cudaGetSymbolAddress((void**)&n1,     g_n1);
    cudaGetSymbolAddress((void**)&rinv,   g_rinv);
    cudaGetSymbolAddress((void**)&pinv,   g_pinv);
    cudaGetSymbolAddress((void**)&qkv,    g_qkv);
    cudaGetSymbolAddress((void**)&scores, g_scores);
    cudaGetSymbolAddress((void**)&att,    g_att);
    cudaGetSymbolAddress((void**)&y,      g_y);
    cudaGetSymbolAddress((void**)&h1,     g_h1);
    cudaGetSymbolAddress((void**)&zin,    g_zin);
    cudaGetSymbolAddress((void**)&xr,     g_xr);
    cudaGetSymbolAddress((void**)&h,      g_h);

    float* out_x = (float*)d_out;
    float* dmap  = (float*)d_out + X_ELEMS;

    const long long sTokQ = (long long)NTOK * 3 * DIMC;   // per-batch stride in qkv
    const long long sS    = (long long)NTOK * NTOK;       // per-(b,h) score stride
    const long long sAtt_b = (long long)NTOK * DIMC;

    // 1. n1 = LN1(x), rinv = 1/||n1|| per token
    ln_kernel<<<MTOK, 256>>>(x, ln1_g, ln1_b, n1, rinv);
    // 2. pinv = 1/||P_k||
    rownorm_kernel<<<KPARTS, 256>>>(P, pinv);
    // 3. qkv = n1 @ qkv_w^T + qkv_b
    gemm_launch<128, 128, true, 0>(n1, qkv_w, qkv, MTOK, 3 * DIMC, DIMC,
        DIMC, DIMC, 3 * DIMC, 1, 1, 0, 0, 0, 0, 0, 0, 0, 0, 0,
        1.f, qkv_b, nullptr, nullptr, nullptr, nullptr);

    // 4-6. attention #1, in Z-chunks of ZCHUNK (b,h) pairs
    for (int z0 = 0; z0 < BATCH * HEADS; z0 += ZCHUNK) {
        // scores[local z] = 0.125 * Q K^T   (A,B global; C chunk-local)
        gemm_launch<128, 128, true, 0>(qkv, qkv + DIMC, scores, NTOK, NTOK, HD,
            3 * DIMC, 3 * DIMC, NTOK, ZCHUNK, HEADS, z0, /*aLocal=*/0, /*cLocal=*/1,
            sTokQ, HD, sTokQ, HD, 0, sS,
            0.125f, nullptr, nullptr, nullptr, nullptr, nullptr);
        softmax1024<<<ZCHUNK * NTOK, 256>>>(scores);
        // att = P V   (A chunk-local scores; B,C global)
        gemm_launch<128, 64, false, 0>(scores, qkv + 2 * DIMC, att, NTOK, HD, NTOK,
            NTOK, 3 * DIMC, DIMC, ZCHUNK, HEADS, z0, /*aLocal=*/1, /*cLocal=*/0,
            0, sS, sTokQ, HD, sAtt_b, HD,
            1.f, nullptr, nullptr, nullptr, nullptr, nullptr);
    }

    // 7. y = att @ proj_w^T + proj_b
    gemm_launch<128, 128, true, 0>(att, proj_w, y, MTOK, DIMC, DIMC,
        DIMC, DIMC, DIMC, 1, 1, 0, 0, 0, 0, 0, 0, 0, 0, 0,
        1.f, proj_b, nullptr, nullptr, nullptr, nullptr);
    // 8. dmap = cosine(n1, P)  -> straight into d_out tail
    gemm_launch<128, 64, true, 2>(n1, P, dmap, MTOK, KPARTS, DIMC,
        DIMC, DIMC, KPARTS, 1, 1, 0, 0, 0, 0, 0, 0, 0, 0, 0,
        1.f, nullptr, nullptr, nullptr, rinv, pinv);
    // 9. h1 = gelu(dmap @ cp_fc1_w^T + b)
    gemm_launch<128, 64, true, 1>(dmap, cp_fc1_w, h1, MTOK, KPARTS, KPARTS,
        KPARTS, KPARTS, KPARTS, 1, 1, 0, 0, 0, 0, 0, 0, 0, 0, 0,
        1.f, cp_fc1_b, nullptr, nullptr, nullptr, nullptr);
    // 10. zin = h1 @ cp_fc2_w^T + b
    gemm_launch<128, 128, true, 0>(h1, cp_fc2_w, zin, MTOK, DIMC, KPARTS,
        KPARTS, KPARTS, DIMC, 1, 1, 0, 0, 0, 0, 0, 0, 0, 0, 0,
        1.f, cp_fc2_b, nullptr, nullptr, nullptr, nullptr);
    // 11. c_qkv (reuse qkv buffer)
    gemm_launch<128, 128, true, 0>(zin, c_qkv_w, qkv, MTOK, 3 * DIMC, DIMC,
        DIMC, DIMC, 3 * DIMC, 1, 1, 0, 0, 0, 0, 0, 0, 0, 0, 0,
        1.f, c_qkv_b, nullptr, nullptr, nullptr, nullptr);

    // 12-14. attention #2 (same chunking)
    for (int z0 = 0; z0 < BATCH * HEADS; z0 += ZCHUNK) {
        gemm_launch<128, 128, true, 0>(qkv, qkv + DIMC, scores, NTOK, NTOK, HD,
            3 * DIMC, 3 * DIMC, NTOK, ZCHUNK, HEADS, z0, 0, 1,
            sTokQ, HD, sTokQ, HD, 0, sS,
            0.125f, nullptr, nullptr, nullptr, nullptr, nullptr);
        softmax1024<<<ZCHUNK * NTOK, 256>>>(scores);
        gemm_launch<128, 64, false, 0>(scores, qkv + 2 * DIMC, att, NTOK, HD, NTOK,
            NTOK, 3 * DIMC, DIMC, ZCHUNK, HEADS, z0, 1, 0,
            0, sS, sTokQ, HD, sAtt_b, HD,
            1.f, nullptr, nullptr, nullptr, nullptr, nullptr);
    }

    // 15. xr = att @ c_proj_w^T + c_proj_b + x + y
    gemm_launch<128, 128, true, 3>(att, c_proj_w, xr, MTOK, DIMC, DIMC,
        DIMC, DIMC, DIMC, 1, 1, 0, 0, 0, 0, 0, 0, 0, 0, 0,
        1.f, c_proj_b, x, y, nullptr, nullptr);
    // 16. n2 = LN2(xr)  (reuse n1 buffer)
    ln_kernel<<<MTOK, 256>>>(xr, ln2_g, ln2_b, n1, nullptr);
    // 17. h = gelu(n2 @ fc1_w^T + fc1_b)
    gemm_launch<128, 128, true, 1>(n1, fc1_w, h, MTOK, MLPH, DIMC,
        DIMC, DIMC, MLPH, 1, 1, 0, 0, 0, 0, 0, 0, 0, 0, 0,
        1.f, fc1_b, nullptr, nullptr, nullptr, nullptr);
    // 18. out_x = h @ fc2_w^T + fc2_b + xr
    gemm_launch<128, 128, true, 3>(h, fc2_w, out_x, MTOK, DIMC, MLPH,
        MLPH, MLPH, DIMC, 1, 1, 0, 0, 0, 0, 0, 0, 0, 0, 0,
        1.f, fc2_b, xr, nullptr, nullptr, nullptr);
}

// round 4
// speedup vs baseline: 1.8667x; 1.8667x over previous
#include <cuda_runtime.h>
#include <cuda_bf16.h>
#include <math.h>

// ---------------------------------------------------------------------------
// Problem constants
// ---------------------------------------------------------------------------
#define MTOK   8192          // 8 * 1024 tokens
#define DIMC   768
#define HEADS  12
#define HD     64
#define KPARTS 64
#define MLPH   3072
#define NTOK   1024
#define BATCH  8
#define X_ELEMS (MTOK * DIMC)
#define DMAP_ELEMS (MTOK * KPARTS)

#define ZCHUNK 48            // (b,h) pairs per attention chunk

// ---------------------------------------------------------------------------
// Scratch (device globals; no allocation allowed)
// ---------------------------------------------------------------------------
__device__ float g_n1   [MTOK * DIMC];
__device__ float g_rinv [MTOK];
__device__ float g_pinv [KPARTS];
__device__ float g_qkv  [MTOK * 3 * DIMC];
__device__ float g_scores[(long long)ZCHUNK * NTOK * NTOK];
__device__ float g_att  [MTOK * DIMC];
__device__ float g_y    [MTOK * DIMC];
__device__ float g_h1   [MTOK * KPARTS];
__device__ float g_zin  [MTOK * DIMC];
__device__ float g_xr   [MTOK * DIMC];
__device__ float g_h    [MTOK * MLPH];

// ---------------------------------------------------------------------------
// Reductions
// ---------------------------------------------------------------------------
__device__ __forceinline__ float blk_sum(float v, float* sbuf) {
    #pragma unroll
    for (int o = 16; o; o >>= 1) v += __shfl_xor_sync(0xffffffffu, v, o);
    if ((threadIdx.x & 31) == 0) sbuf[threadIdx.x >> 5] = v;
    __syncthreads();
    if (threadIdx.x == 0) {
        float r = sbuf[0];
        int nw = blockDim.x >> 5;
        for (int i = 1; i < nw; i++) r += sbuf[i];
        sbuf[0] = r;
    }
    __syncthreads();
    float r = sbuf[0];
    __syncthreads();
    return r;
}

__device__ __forceinline__ float blk_max(float v, float* sbuf) {
    #pragma unroll
    for (int o = 16; o; o >>= 1) v = fmaxf(v, __shfl_xor_sync(0xffffffffu, v, o));
    if ((threadIdx.x & 31) == 0) sbuf[threadIdx.x >> 5] = v;
    __syncthreads();
    if (threadIdx.x == 0) {
        float r = sbuf[0];
        int nw = blockDim.x >> 5;
        for (int i = 1; i < nw; i++) r = fmaxf(r, sbuf[i]);
        sbuf[0] = r;
    }
    __syncthreads();
    float r = sbuf[0];
    __syncthreads();
    return r;
}

// ---------------------------------------------------------------------------
// LayerNorm (row = 768), optional row-norm output for cosine map.
// ---------------------------------------------------------------------------
__global__ void ln_kernel(const float* __restrict__ x, const float* __restrict__ g,
                          const float* __restrict__ b, float* __restrict__ out,
                          float* __restrict__ rinv) {
    __shared__ float sbuf[8];
    long long row = blockIdx.x;
    const float* xr = x + row * DIMC;
    float v[3];
    float s = 0.f;
    #pragma unroll
    for (int k = 0; k < 3; k++) { v[k] = xr[threadIdx.x + 256 * k]; s += v[k]; }
    float mu = blk_sum(s, sbuf) * (1.f / DIMC);
    float s2 = 0.f;
    #pragma unroll
    for (int k = 0; k < 3; k++) { float d = v[k] - mu; s2 += d * d; }
    float var = blk_sum(s2, sbuf) * (1.f / DIMC);
    float rs = rsqrtf(var + 1e-5f);
    float sq = 0.f;
    #pragma unroll
    for (int k = 0; k < 3; k++) {
        int c = threadIdx.x + 256 * k;
        float yv = (v[k] - mu) * rs * g[c] + b[c];
        out[row * DIMC + c] = yv;
        sq += yv * yv;
    }
    if (rinv) {
        float nn = blk_sum(sq, sbuf);
        if (threadIdx.x == 0) rinv[row] = 1.f / sqrtf(nn);
    }
}

__global__ void rownorm_kernel(const float* __restrict__ P, float* __restrict__ pinv) {
    __shared__ float sbuf[8];
    const float* r = P + (long long)blockIdx.x * DIMC;
    float s = 0.f;
    for (int k = threadIdx.x; k < DIMC; k += 256) { float v = r[k]; s += v * v; }
    s = blk_sum(s, sbuf);
    if (threadIdx.x == 0) pinv[blockIdx.x] = 1.f / sqrtf(s);
}

__global__ void softmax1024(float* __restrict__ S) {
    __shared__ float sbuf[8];
    float4* row = (float4*)(S + (long long)blockIdx.x * NTOK);
    float4 v = row[threadIdx.x];
    float mx = fmaxf(fmaxf(v.x, v.y), fmaxf(v.z, v.w));
    mx = blk_max(mx, sbuf);
    v.x = expf(v.x - mx); v.y = expf(v.y - mx);
    v.z = expf(v.z - mx); v.w = expf(v.w - mx);
    float s = blk_sum(v.x + v.y + v.z + v.w, sbuf);
    float inv = 1.f / s;
    v.x *= inv; v.y *= inv; v.z *= inv; v.w *= inv;
    row[threadIdx.x] = v;
}

// ---------------------------------------------------------------------------
// bf16x3 tensor-core GEMM.
//   fp32 operands split on-the-fly: x = hi(bf16) + lo(bf16); product computed
//   as hi*hi + hi*lo + lo*hi via mma.sync.m16n8k16 (f32 accumulate).
//   TRB=true : C = alpha * A[M,K] * B[N,K]^T
//   TRB=false: C = alpha * A[M,K] * B[K,N]
// Batching over blockIdx.z with aLocal/cLocal chunk-local addressing.
// EPI: 0 none, 1 exact GELU, 2 row*col scale, 3 residual add(s).
// ---------------------------------------------------------------------------
__device__ __forceinline__ void mma16816(float* d, const unsigned* a, const unsigned* b) {
    asm volatile(
        "mma.sync.aligned.m16n8k16.row.col.f32.bf16.bf16.f32 "
        "{%0,%1,%2,%3}, {%4,%5,%6,%7}, {%8,%9}, {%0,%1,%2,%3};\n"
        : "+f"(d[0]), "+f"(d[1]), "+f"(d[2]), "+f"(d[3])
        : "r"(a[0]), "r"(a[1]), "r"(a[2]), "r"(a[3]), "r"(b[0]), "r"(b[1]));
}

__device__ __forceinline__ void split_bf16(float x, __nv_bfloat16& h, __nv_bfloat16& l) {
    h = __float2bfloat16(x);
    l = __float2bfloat16(x - __bfloat162float(h));
}

template<int BM, int BN, int BK, int WGM, int WGN, int WM, int WN, bool TRB, int EPI>
__global__ void __launch_bounds__(WGM * WGN * 32, 2)
bgemm_k(const float* __restrict__ A, const float* __restrict__ B, float* __restrict__ C,
        int K, int lda, int ldb, int ldc, int NH, int zoff, int aLocal, int cLocal,
        long long sAb, long long sAh, long long sBb, long long sBh,
        long long sCb, long long sCh,
        float alpha,
        const float* __restrict__ bias,
        const float* __restrict__ res1, const float* __restrict__ res2,
        const float* __restrict__ rowscale, const float* __restrict__ colscale) {
    constexpr int NT = WGM * WGN * 32;
    constexpr int MF = WM / 16;
    constexpr int NF = WN / 8;
    constexpr int KP = BK + 2;
    static_assert(WGM * WM == BM && WGN * WN == BN, "tile mismatch");

    __shared__ __nv_bfloat16 Ah[BM][KP], Al[BM][KP];
    __shared__ __nv_bfloat16 Bh[BN][KP], Bl[BN][KP];

    const int tid = threadIdx.x;
    const int warp = tid >> 5, lane = tid & 31;
    const int g = lane >> 2, t = lane & 3;
    const int wm0 = (warp / WGN) * WM, wn0 = (warp % WGN) * WN;
    const int bx = blockIdx.x, by = blockIdx.y;
    const int bzg = blockIdx.z + zoff;
    const int zb = bzg / NH, zh = bzg % NH;

    const float* Ab = A
        + (aLocal ? (long long)blockIdx.z * sAh
                  : (long long)zb * sAb + (long long)zh * sAh)
        + (long long)by * BM * lda;
    const float* Bb = B + (long long)zb * sBb + (long long)zh * sBh +
                      (TRB ? (long long)bx * BN * ldb : (long long)(bx * BN));
    float* Cb = C
        + (cLocal ? (long long)blockIdx.z * sCh
                  : (long long)zb * sCb + (long long)zh * sCh)
        + (long long)by * BM * ldc + (long long)(bx * BN);

    float acc[MF][NF][4] = {};

    for (int k0 = 0; k0 < K; k0 += BK) {
        // --- fill A tile (row-major [m][k], split hi/lo) ---
        #pragma unroll
        for (int idx = tid; idx < BM * (BK / 4); idx += NT) {
            int row = idx / (BK / 4), c4 = idx % (BK / 4);
            float4 v = *(const float4*)(Ab + (long long)row * lda + k0 + 4 * c4);
            __nv_bfloat16 h0, h1, h2, h3, l0, l1, l2, l3;
            split_bf16(v.x, h0, l0); split_bf16(v.y, h1, l1);
            split_bf16(v.z, h2, l2); split_bf16(v.w, h3, l3);
            int kk = 4 * c4;
            *(__nv_bfloat162*)&Ah[row][kk]     = __halves2bfloat162(h0, h1);
            *(__nv_bfloat162*)&Ah[row][kk + 2] = __halves2bfloat162(h2, h3);
            *(__nv_bfloat162*)&Al[row][kk]     = __halves2bfloat162(l0, l1);
            *(__nv_bfloat162*)&Al[row][kk + 2] = __halves2bfloat162(l2, l3);
        }
        // --- fill B tile into [n][k] layout ---
        if (TRB) {
            #pragma unroll
            for (int idx = tid; idx < BN * (BK / 4); idx += NT) {
                int row = idx / (BK / 4), c4 = idx % (BK / 4);
                float4 v = *(const float4*)(Bb + (long long)row * ldb + k0 + 4 * c4);
                __nv_bfloat16 h0, h1, h2, h3, l0, l1, l2, l3;
                split_bf16(v.x, h0, l0); split_bf16(v.y, h1, l1);
                split_bf16(v.z, h2, l2); split_bf16(v.w, h3, l3);
                int kk = 4 * c4;
                *(__nv_bfloat162*)&Bh[row][kk]     = __halves2bfloat162(h0, h1);
                *(__nv_bfloat162*)&Bh[row][kk + 2] = __halves2bfloat162(h2, h3);
                *(__nv_bfloat162*)&Bl[row][kk]     = __halves2bfloat162(l0, l1);
                *(__nv_bfloat162*)&Bl[row][kk + 2] = __halves2bfloat162(l2, l3);
            }
        } else {
            #pragma unroll
            for (int idx = tid; idx < BK * (BN / 4); idx += NT) {
                int kr = idx / (BN / 4), c4 = idx % (BN / 4);
                float4 v = *(const float4*)(Bb + (long long)(k0 + kr) * ldb + 4 * c4);
                int n0 = 4 * c4;
                __nv_bfloat16 h, l;
                split_bf16(v.x, h, l); Bh[n0 + 0][kr] = h; Bl[n0 + 0][kr] = l;
                split_bf16(v.y, h, l); Bh[n0 + 1][kr] = h; Bl[n0 + 1][kr] = l;
                split_bf16(v.z, h, l); Bh[n0 + 2][kr] = h; Bl[n0 + 2][kr] = l;
                split_bf16(v.w, h, l); Bh[n0 + 3][kr] = h; Bl[n0 + 3][kr] = l;
            }
        }
        __syncthreads();

        #pragma unroll
        for (int ks = 0; ks < BK / 16; ks++) {
            const int kk = ks * 16 + t * 2;
            unsigned Ar[MF][4], Br[NF][2], Bs2[NF][2];
            // A_hi frags
            #pragma unroll
            for (int fm = 0; fm < MF; fm++) {
                int r0 = wm0 + fm * 16 + g;
                Ar[fm][0] = *(const unsigned*)&Ah[r0][kk];
                Ar[fm][1] = *(const unsigned*)&Ah[r0 + 8][kk];
                Ar[fm][2] = *(const unsigned*)&Ah[r0][kk + 8];
                Ar[fm][3] = *(const unsigned*)&Ah[r0 + 8][kk + 8];
            }
            // B_hi frags
            #pragma unroll
            for (int fn = 0; fn < NF; fn++) {
                int n0 = wn0 + fn * 8 + g;
                Br[fn][0] = *(const unsigned*)&Bh[n0][kk];
                Br[fn][1] = *(const unsigned*)&Bh[n0][kk + 8];
            }
            // hi * hi
            #pragma unroll
            for (int fm = 0; fm < MF; fm++)
                #pragma unroll
                for (int fn = 0; fn < NF; fn++)
                    mma16816(acc[fm][fn], Ar[fm], Br[fn]);
            // B_lo frags; hi * lo
            #pragma unroll
            for (int fn = 0; fn < NF; fn++) {
                int n0 = wn0 + fn * 8 + g;
                Bs2[fn][0] = *(const unsigned*)&Bl[n0][kk];
                Bs2[fn][1] = *(const unsigned*)&Bl[n0][kk + 8];
            }
            #pragma unroll
            for (int fm = 0; fm < MF; fm++)
                #pragma unroll
                for (int fn = 0; fn < NF; fn++)
                    mma16816(acc[fm][fn], Ar[fm], Bs2[fn]);
            // A_lo frags (overwrite Ar); lo * hi
            #pragma unroll
            for (int fm = 0; fm < MF; fm++) {
                int r0 = wm0 + fm * 16 + g;
                Ar[fm][0] = *(const unsigned*)&Al[r0][kk];
                Ar[fm][1] = *(const unsigned*)&Al[r0 + 8][kk];
                Ar[fm][2] = *(const unsigned*)&Al[r0][kk + 8];
                Ar[fm][3] = *(const unsigned*)&Al[r0 + 8][kk + 8];
            }
            #pragma unroll
            for (int fm = 0; fm < MF; fm++)
                #pragma unroll
                for (int fn = 0; fn < NF; fn++)
                    mma16816(acc[fm][fn], Ar[fm], Br[fn]);
        }
        __syncthreads();
    }

    // --- epilogue ---
    #pragma unroll
    for (int fm = 0; fm < MF; fm++) {
        #pragma unroll
        for (int fn = 0; fn < NF; fn++) {
            #pragma unroll
            for (int h = 0; h < 2; h++) {
                int lrow = wm0 + fm * 16 + g + h * 8;
                long long m = (long long)by * BM + lrow;
                #pragma unroll
                for (int j = 0; j < 2; j++) {
                    int lcol = wn0 + fn * 8 + t * 2 + j;
                    int n = bx * BN + lcol;
                    float v = acc[fm][fn][h * 2 + j] * alpha;
                    if (bias) v += bias[n];
                    if constexpr (EPI == 1)
                        v = 0.5f * v * (1.f + erff(v * 0.70710678118654752f));
                    if constexpr (EPI == 2)
                        v *= rowscale[m] * colscale[n];
                    if constexpr (EPI == 3) {
                        v += res1[m * ldc + n];
                        if (res2) v += res2[m * ldc + n];
                    }
                    Cb[(long long)lrow * ldc + lcol] = v;
                }
            }
        }
    }
}

// ---------------------------------------------------------------------------
// Launch helpers: 128x128 and 128x64 tile configs, 8 warps.
// ---------------------------------------------------------------------------
template<bool TRB, int EPI>
static void gemm128(const float* A, const float* B, float* C,
                    int Mrows, int Ncols, int K,
                    int lda, int ldb, int ldc,
                    int nbz, int NH, int zoff, int aLocal, int cLocal,
                    long long sAb, long long sAh, long long sBb, long long sBh,
                    long long sCb, long long sCh,
                    float alpha, const float* bias,
                    const float* res1, const float* res2,
                    const float* rs, const float* cs) {
    dim3 grid(Ncols / 128, Mrows / 128, nbz);
    bgemm_k<128, 128, 32, 2, 4, 64, 32, TRB, EPI><<<grid, 256>>>(
        A, B, C, K, lda, ldb, ldc, NH, zoff, aLocal, cLocal,
        sAb, sAh, sBb, sBh, sCb, sCh, alpha, bias, res1, res2, rs, cs);
}

template<bool TRB, int EPI>
static void gemm64(const float* A, const float* B, float* C,
                   int Mrows, int Ncols, int K,
                   int lda, int ldb, int ldc,
                   int nbz, int NH, int zoff, int aLocal, int cLocal,
                   long long sAb, long long sAh, long long sBb, long long sBh,
                   long long sCb, long long sCh,
                   float alpha, const float* bias,
                   const float* res1, const float* res2,
                   const float* rs, const float* cs) {
    dim3 grid(Ncols / 64, Mrows / 128, nbz);
    bgemm_k<128, 64, 32, 2, 4, 64, 16, TRB, EPI><<<grid, 256>>>(
        A, B, C, K, lda, ldb, ldc, NH, zoff, aLocal, cLocal,
        sAb, sAh, sBb, sBh, sCb, sCh, alpha, bias, res1, res2, rs, cs);
}

// ---------------------------------------------------------------------------
// kernel_launch
// ---------------------------------------------------------------------------
extern "C" void kernel_launch(void* const* d_in, const int* in_sizes, int n_in,
                              void* d_out, int out_size) {
    const float* x        = (const float*)d_in[0];
    const float* ln1_g    = (const float*)d_in[1];
    const float* ln1_b    = (const float*)d_in[2];
    const float* qkv_w    = (const float*)d_in[3];
    const float* qkv_b    = (const float*)d_in[4];
    const float* proj_w   = (const float*)d_in[5];
    const float* proj_b   = (const float*)d_in[6];
    const float* c_qkv_w  = (const float*)d_in[7];
    const float* c_qkv_b  = (const float*)d_in[8];
    const float* c_proj_w = (const float*)d_in[9];
    const float* c_proj_b = (const float*)d_in[10];
    const float* cp_fc1_w = (const float*)d_in[11];
    const float* cp_fc1_b = (const float*)d_in[12];
    const float* cp_fc2_w = (const float*)d_in[13];
    const float* cp_fc2_b = (const float*)d_in[14];
    const float* P        = (const float*)d_in[15];
    const float* ln2_g    = (const float*)d_in[16];
    const float* ln2_b    = (const float*)d_in[17];
    const float* fc1_w    = (const float*)d_in[18];
    const float* fc1_b    = (const float*)d_in[19];
    const float* fc2_w    = (const float*)d_in[20];
    const float* fc2_b    = (const float*)d_in[21];

    float *n1, *rinv, *pinv, *qkv, *scores, *att, *y, *h1, *zin, *xr, *h;
    cudaGetSymbolAddress((void**)&n1,     g_n1);
    cudaGetSymbolAddress((void**)&rinv,   g_rinv);
    cudaGetSymbolAddress((void**)&pinv,   g_pinv);
    cudaGetSymbolAddress((void**)&qkv,    g_qkv);
    cudaGetSymbolAddress((void**)&scores, g_scores);
    cudaGetSymbolAddress((void**)&att,    g_att);
    cudaGetSymbolAddress((void**)&y,      g_y);
    cudaGetSymbolAddress((void**)&h1,     g_h1);
    cudaGetSymbolAddress((void**)&zin,    g_zin);
    cudaGetSymbolAddress((void**)&xr,     g_xr);
    cudaGetSymbolAddress((void**)&h,      g_h);

    float* out_x = (float*)d_out;
    float* dmap  = (float*)d_out + X_ELEMS;

    const long long sTokQ = (long long)NTOK * 3 * DIMC;
    const long long sS    = (long long)NTOK * NTOK;
    const long long sAtt_b = (long long)NTOK * DIMC;

    // 1. n1 = LN1(x), rinv = 1/||n1||
    ln_kernel<<<MTOK, 256>>>(x, ln1_g, ln1_b, n1, rinv);
    // 2. pinv
    rownorm_kernel<<<KPARTS, 256>>>(P, pinv);
    // 3. qkv = n1 @ qkv_w^T + qkv_b
    gemm128<true, 0>(n1, qkv_w, qkv, MTOK, 3 * DIMC, DIMC,
        DIMC, DIMC, 3 * DIMC, 1, 1, 0, 0, 0, 0, 0, 0, 0, 0, 0,
        1.f, qkv_b, nullptr, nullptr, nullptr, nullptr);

    // 4-6. attention #1
    for (int z0 = 0; z0 < BATCH * HEADS; z0 += ZCHUNK) {
        gemm128<true, 0>(qkv, qkv + DIMC, scores, NTOK, NTOK, HD,
            3 * DIMC, 3 * DIMC, NTOK, ZCHUNK, HEADS, z0, 0, 1,
            sTokQ, HD, sTokQ, HD, 0, sS,
            0.125f, nullptr, nullptr, nullptr, nullptr, nullptr);
        softmax1024<<<ZCHUNK * NTOK, 256>>>(scores);
        gemm64<false, 0>(scores, qkv + 2 * DIMC, att, NTOK, HD, NTOK,
            NTOK, 3 * DIMC, DIMC, ZCHUNK, HEADS, z0, 1, 0,
            0, sS, sTokQ, HD, sAtt_b, HD,
            1.f, nullptr, nullptr, nullptr, nullptr, nullptr);
    }

    // 7. y = att @ proj_w^T + proj_b
    gemm128<true, 0>(att, proj_w, y, MTOK, DIMC, DIMC,
        DIMC, DIMC, DIMC, 1, 1, 0, 0, 0, 0, 0, 0, 0, 0, 0,
        1.f, proj_b, nullptr, nullptr, nullptr, nullptr);
    // 8. dmap = cosine(n1, P)
    gemm64<true, 2>(n1, P, dmap, MTOK, KPARTS, DIMC,
        DIMC, DIMC, KPARTS, 1, 1, 0, 0, 0, 0, 0, 0, 0, 0, 0,
        1.f, nullptr, nullptr, nullptr, rinv, pinv);
    // 9. h1 = gelu(dmap @ cp_fc1_w^T + b)
    gemm64<true, 1>(dmap, cp_fc1_w, h1, MTOK, KPARTS, KPARTS,
        KPARTS, KPARTS, KPARTS, 1, 1, 0, 0, 0, 0, 0, 0, 0, 0, 0,
        1.f, cp_fc1_b, nullptr, nullptr, nullptr, nullptr);
    // 10. zin = h1 @ cp_fc2_w^T + b
    gemm128<true, 0>(h1, cp_fc2_w, zin, MTOK, DIMC, KPARTS,
        KPARTS, KPARTS, DIMC, 1, 1, 0, 0, 0, 0, 0, 0, 0, 0, 0,
        1.f, cp_fc2_b, nullptr, nullptr, nullptr, nullptr);
    // 11. c_qkv (reuse qkv buffer)
    gemm128<true, 0>(zin, c_qkv_w, qkv, MTOK, 3 * DIMC, DIMC,
        DIMC, DIMC, 3 * DIMC, 1, 1, 0, 0, 0, 0, 0, 0, 0, 0, 0,
        1.f, c_qkv_b, nullptr, nullptr, nullptr, nullptr);

    // 12-14. attention #2
    for (int z0 = 0; z0 < BATCH * HEADS; z0 += ZCHUNK) {
        gemm128<true, 0>(qkv, qkv + DIMC, scores, NTOK, NTOK, HD,
            3 * DIMC, 3 * DIMC, NTOK, ZCHUNK, HEADS, z0, 0, 1,
            sTokQ, HD, sTokQ, HD, 0, sS,
            0.125f, nullptr, nullptr, nullptr, nullptr, nullptr);
        softmax1024<<<ZCHUNK * NTOK, 256>>>(scores);
        gemm64<false, 0>(scores, qkv + 2 * DIMC, att, NTOK, HD, NTOK,
            NTOK, 3 * DIMC, DIMC, ZCHUNK, HEADS, z0, 1, 0,
            0, sS, sTokQ, HD, sAtt_b, HD,
            1.f, nullptr, nullptr, nullptr, nullptr, nullptr);
    }

    // 15. xr = att @ c_proj_w^T + c_proj_b + x + y
    gemm128<true, 3>(att, c_proj_w, xr, MTOK, DIMC, DIMC,
        DIMC, DIMC, DIMC, 1, 1, 0, 0, 0, 0, 0, 0, 0, 0, 0,
        1.f, c_proj_b, x, y, nullptr, nullptr);
    // 16. n2 = LN2(xr)
    ln_kernel<<<MTOK, 256>>>(xr, ln2_g, ln2_b, n1, nullptr);
    // 17. h = gelu(n2 @ fc1_w^T + fc1_b)
    gemm128<true, 1>(n1, fc1_w, h, MTOK, MLPH, DIMC,
        DIMC, DIMC, MLPH, 1, 1, 0, 0, 0, 0, 0, 0, 0, 0, 0,
        1.f, fc1_b, nullptr, nullptr, nullptr, nullptr);
    // 18. out_x = h @ fc2_w^T + fc2_b + xr
    gemm128<true, 3>(h, fc2_w, out_x, MTOK, DIMC, MLPH,
        MLPH, MLPH, DIMC, 1, 1, 0, 0, 0, 0, 0, 0, 0, 0, 0,
        1.f, fc2_b, xr, nullptr, nullptr, nullptr);
}